// round 1
// baseline (speedup 1.0000x reference)
#include <cuda_runtime.h>
#include <cstdint>

// BestChangeLayer: B=1024 batches, 25x25 binary grids, 512 candidate 3x3
// patterns, one Conway step on a 7x7 window, L1 error on inner 5x5 vs target,
// argmin(err + 0.5*noise), write winning pattern into x at (ry, rx).
//
// Bitboard encoding: 7x7 board packed in u64, bit (r*8 + c), r,c in 0..6.

#define NPAT 512

__global__ __launch_bounds__(512, 2)
void bcl_kernel(const float* __restrict__ x,
                const float* __restrict__ target,
                const float* __restrict__ noise,
                const int* __restrict__ ryp,
                const int* __restrict__ rxp,
                float* __restrict__ out)
{
    const int b = blockIdx.x;
    const int t = threadIdx.x;
    const int ry = *ryp;
    const int rx = *rxp;

    const float* __restrict__ xb = x + b * 625;
    const float* __restrict__ tb = target + b * 625;
    float* __restrict__ ob = out + b * 625;

    __shared__ unsigned long long s_fixed;  // 7x7 influence, center 3x3 cleared
    __shared__ unsigned long long s_targ;   // 5x5 target at rows/cols 1..5
    __shared__ float sv[NPAT];
    __shared__ int   si[NPAT];

    if (t == 0) { s_fixed = 0ULL; s_targ = 0ULL; }
    __syncthreads();

    // Cooperative gather of the two windows (periodic padding => mod 25).
    if (t < 49) {
        int r = t / 7, c = t % 7;
        bool center = (r >= 2 && r <= 4 && c >= 2 && c <= 4);
        if (!center) {
            int rr = (ry - 2 + r) % 25; if (rr < 0) rr += 25;
            int cc = (rx - 2 + c) % 25; if (cc < 0) cc += 25;
            if (xb[rr * 25 + cc] != 0.0f)
                atomicOr(&s_fixed, 1ULL << (r * 8 + c));
        }
    } else if (t < 74) {
        int k = t - 49;
        int r = k / 5, c = k % 5;
        int rr = (ry - 1 + r) % 25; if (rr < 0) rr += 25;
        int cc = (rx - 1 + c) % 25; if (cc < 0) cc += 25;
        if (tb[rr * 25 + cc] != 0.0f)
            atomicOr(&s_targ, 1ULL << ((r + 1) * 8 + (c + 1)));
    }

    // Overlap: copy this batch's x into out while the gather settles.
    for (int i = t; i < 625; i += NPAT) ob[i] = xb[i];

    __syncthreads();

    // Build this thread's board: fixed part + pattern p = t in the center 3x3.
    // pi[p][r][c] = (p >> (8 - (r*3+c))) & 1.
    const int p = t;
    unsigned long long board = s_fixed;
    #pragma unroll
    for (int k = 0; k < 9; k++) {
        int r = k / 3, c = k % 3;
        if (p & (1 << (8 - k)))
            board |= 1ULL << ((2 + r) * 8 + (2 + c));
    }

    // One Conway step, bit-parallel (carry-save adders).
    const unsigned long long M = 0x007F7F7F7F7F7F7FULL;  // rows 0..6, cols 0..6+guard
    unsigned long long n1 = (board << 1) & M;   // west neighbor value at cell
    unsigned long long n2 = (board >> 1) & M;   // east
    unsigned long long n3 = board << 8;         // north
    unsigned long long n4 = board >> 8;         // south
    unsigned long long n5 = n1 << 8;            // NW
    unsigned long long n6 = n1 >> 8;            // SW
    unsigned long long n7 = n2 << 8;            // NE
    unsigned long long n8 = n2 >> 8;            // SE

    unsigned long long A = n1 ^ n2, Bb = n1 & n2;
    unsigned long long C = n3 ^ n4, D  = n3 & n4;
    unsigned long long E = n5 ^ n6, F  = n5 & n6;
    unsigned long long G = n7 ^ n8, H  = n7 & n8;

    unsigned long long s1a = A ^ C, c1a = A & C;
    unsigned long long s1b = E ^ G, c1b = E & G;
    unsigned long long lo  = s1a ^ s1b, clo = s1a & s1b;  // bit0 of neighbor count

    // t2 = Bb+D+F+H+c1a+c1b+clo (weight-2 units). Need (count>>1) == 1 exactly.
    unsigned long long u = Bb ^ D,  uc = Bb & D;
    unsigned long long v = F  ^ H,  vc = F  & H;
    unsigned long long w = c1a ^ c1b, wc = c1a & c1b;
    unsigned long long pp = u ^ v,  pc = u & v;
    unsigned long long q  = pp ^ w, qc = pp & w;
    unsigned long long r0 = q ^ clo, rc = q & clo;
    unsigned long long K  = uc | vc | wc | pc | qc | rc;  // t2 >= 2

    // next alive iff count==3 (lo=1,t2=1) or (alive and count==2: lo=0,t2=1)
    unsigned long long next = r0 & ~K & (lo | board);

    const unsigned long long CROP = 0x00003E3E3E3E3E00ULL;  // rows 1..5, cols 1..5
    int err = __popcll((next & CROP) ^ s_targ);

    float seeded = (float)err + noise[b * NPAT + p] * 0.5f;

    // Block argmin with first-index tiebreak (matches jnp.argmin).
    sv[t] = seeded;
    si[t] = t;
    __syncthreads();
    #pragma unroll
    for (int s = NPAT / 2; s > 0; s >>= 1) {
        if (t < s) {
            float v2 = sv[t + s];
            int   i2 = si[t + s];
            if (v2 < sv[t] || (v2 == sv[t] && i2 < si[t])) { sv[t] = v2; si[t] = i2; }
        }
        __syncthreads();
    }
    int best = si[0];

    // Overwrite the 3x3 region with the winning pattern (no wrap per reference).
    if (t < 9) {
        int r = t / 3, c = t % 3;
        float vv = (best & (1 << (8 - t))) ? 1.0f : 0.0f;
        ob[(ry + r) * 25 + (rx + c)] = vv;
    }
}

extern "C" void kernel_launch(void* const* d_in, const int* in_sizes, int n_in,
                              void* d_out, int out_size)
{
    const float* x      = (const float*)d_in[0];
    const float* target = (const float*)d_in[1];
    const float* noise  = (const float*)d_in[2];
    const int*   ryp    = (const int*)d_in[3];
    const int*   rxp    = (const int*)d_in[4];
    float* out = (float*)d_out;

    int B = in_sizes[0] / 625;
    bcl_kernel<<<B, NPAT>>>(x, target, noise, ryp, rxp, out);
}

// round 2
// speedup vs baseline: 1.3468x; 1.3468x over previous
#include <cuda_runtime.h>
#include <cstdint>

// BestChangeLayer: B batches, 25x25 binary grids, 512 candidate 3x3 patterns,
// one Conway step on a 7x7 window, L1 error on inner 5x5 vs target,
// argmin(err + 0.5*noise), write winning pattern into x at (ry, rx).
//
// Bitboards: 7x7 packed in u64 at bit (r*8 + c).
// 2 warps per batch, 8 patterns per lane, warp-shuffle argmin on packed keys.

#define NPAT 512
typedef unsigned long long u64;

__global__ __launch_bounds__(256, 4)
void bcl_kernel(const float* __restrict__ x,
                const float* __restrict__ target,
                const float* __restrict__ noise,
                const int* __restrict__ ryp,
                const int* __restrict__ rxp,
                float* __restrict__ out,
                int B)
{
    __shared__ u64 s_pat[NPAT];   // pattern center masks
    __shared__ u64 s_best[4];     // per-batch best (fbits<<32 | idx)

    const int tid  = threadIdx.x;
    const int warp = tid >> 5;
    const int lane = tid & 31;
    const int wb   = warp >> 1;   // local batch slot 0..3
    const int half = warp & 1;    // which 32-pattern half per iteration
    const int b    = blockIdx.x * 4 + wb;

    // Build pattern LUT once per block. pi bit k (k=r*3+c) = (p >> (8-k)) & 1.
    // Row triple of p is bit-reversed relative to board column order.
    for (int p = tid; p < NPAT; p += 256) {
        u64 m = 0;
        #pragma unroll
        for (int r = 0; r < 3; r++) {
            unsigned t3 = (p >> (6 - 3 * r)) & 7u;
            unsigned rv = __brev(t3) >> 29;          // reverse 3 bits
            m |= (u64)rv << ((2 + r) * 8 + 2);
        }
        s_pat[p] = m;
    }
    if (tid < 4) s_best[tid] = ~0ULL;
    __syncthreads();

    if (b < B) {
        const int ry = *ryp, rx = *rxp;
        const float* __restrict__ xb = x + b * 625;
        const float* __restrict__ tb = target + b * 625;
        float* __restrict__ ob = out + b * 625;

        // Copy this batch's x -> out across the warp pair (64 lanes).
        for (int i = half * 32 + lane; i < 625; i += 64) ob[i] = xb[i];

        // Gather 7x7 influence window (center 3x3 cleared) and 5x5 target
        // window with periodic indexing; OR-reduce bit masks across the warp.
        u64 pf = 0, pt = 0;
        for (int item = lane; item < 74; item += 32) {
            if (item < 49) {
                int r = item / 7, c = item % 7;
                if (!(r >= 2 && r <= 4 && c >= 2 && c <= 4)) {
                    int rr = (ry + 23 + r) % 25;   // ry - 2 + r, wrapped
                    int cc = (rx + 23 + c) % 25;
                    if (xb[rr * 25 + cc] != 0.0f) pf |= 1ULL << (r * 8 + c);
                }
            } else {
                int k = item - 49, r = k / 5, c = k % 5;
                int rr = (ry + 24 + r) % 25;       // ry - 1 + r, wrapped
                int cc = (rx + 24 + c) % 25;
                if (tb[rr * 25 + cc] != 0.0f) pt |= 1ULL << ((r + 1) * 8 + (c + 1));
            }
        }
        u64 fixedB = ((u64)__reduce_or_sync(0xffffffffu, (unsigned)(pf >> 32)) << 32)
                   |  (u64)__reduce_or_sync(0xffffffffu, (unsigned)pf);
        u64 targ   = ((u64)__reduce_or_sync(0xffffffffu, (unsigned)(pt >> 32)) << 32)
                   |  (u64)__reduce_or_sync(0xffffffffu, (unsigned)pt);

        const u64 M    = 0x007F7F7F7F7F7F7FULL;  // col-shift guard
        const u64 CROP = 0x00003E3E3E3E3E00ULL;  // rows 1..5, cols 1..5

        u64 bestKey = ~0ULL;
        #pragma unroll
        for (int i = 0; i < 8; i++) {
            const int p = i * 64 + half * 32 + lane;
            u64 board = fixedB | s_pat[p];

            // One Conway step, bit-parallel (carry-save adders).
            u64 n1 = (board << 1) & M;
            u64 n2 = (board >> 1) & M;
            u64 n3 = board << 8;
            u64 n4 = board >> 8;
            u64 n5 = n1 << 8, n6 = n1 >> 8;
            u64 n7 = n2 << 8, n8 = n2 >> 8;

            u64 A = n1 ^ n2, Bb = n1 & n2;
            u64 C = n3 ^ n4, D  = n3 & n4;
            u64 E = n5 ^ n6, F  = n5 & n6;
            u64 G = n7 ^ n8, H  = n7 & n8;

            u64 s1a = A ^ C, c1a = A & C;
            u64 s1b = E ^ G, c1b = E & G;
            u64 lo  = s1a ^ s1b, clo = s1a & s1b;

            u64 u = Bb ^ D,  uc = Bb & D;
            u64 v = F  ^ H,  vc = F  & H;
            u64 w = c1a ^ c1b, wc = c1a & c1b;
            u64 pp = u ^ v,  pc = u & v;
            u64 q  = pp ^ w, qc = pp & w;
            u64 r0 = q ^ clo, rc = q & clo;
            u64 K  = uc | vc | wc | pc | qc | rc;

            u64 next = r0 & ~K & (lo | board);

            int err = __popcll((next & CROP) ^ targ);
            float seeded = (float)err + noise[b * NPAT + p] * 0.5f;
            u64 key = ((u64)__float_as_uint(seeded) << 32) | (unsigned)p;
            if (key < bestKey) bestKey = key;
        }

        // Warp argmin (packed key => value min with first-index tiebreak).
        #pragma unroll
        for (int s = 16; s; s >>= 1) {
            u64 o = __shfl_xor_sync(0xffffffffu, bestKey, s);
            if (o < bestKey) bestKey = o;
        }
        if (lane == 0) atomicMin(&s_best[wb], bestKey);
    }
    __syncthreads();   // orders copy stores before patch stores, publishes s_best

    if (b < B && half == 0 && lane < 9) {
        int best = (int)(unsigned)s_best[wb];
        float vv = ((best >> (8 - lane)) & 1) ? 1.0f : 0.0f;
        out[b * 625 + (*ryp + lane / 3) * 25 + (*rxp + lane % 3)] = vv;
    }
}

extern "C" void kernel_launch(void* const* d_in, const int* in_sizes, int n_in,
                              void* d_out, int out_size)
{
    const float* x      = (const float*)d_in[0];
    const float* target = (const float*)d_in[1];
    const float* noise  = (const float*)d_in[2];
    const int*   ryp    = (const int*)d_in[3];
    const int*   rxp    = (const int*)d_in[4];
    float* out = (float*)d_out;

    int B = in_sizes[0] / 625;
    bcl_kernel<<<(B + 3) / 4, 256>>>(x, target, noise, ryp, rxp, out, B);
}

// round 3
// speedup vs baseline: 1.3547x; 1.0058x over previous
#include <cuda_runtime.h>
#include <cstdint>

// BestChangeLayer: B batches, 25x25 binary grids, 512 candidate 3x3 patterns,
// one Conway step on a 7x7 window, L1 error on inner 5x5 vs target,
// argmin(err + 0.5*noise), write winning pattern into x at (ry, rx).
//
// Bitboards: 7x7 packed in u64 at bit (r*8 + c).
// One batch per 256-thread block; 2 patterns per lane; warp-shuffle argmin.

#define NPAT 512
typedef unsigned long long u64;

__global__ __launch_bounds__(256, 5)
void bcl_kernel(const float* __restrict__ x,
                const float* __restrict__ target,
                const float* __restrict__ noise,
                const int* __restrict__ ryp,
                const int* __restrict__ rxp,
                float* __restrict__ out)
{
    __shared__ u64 s_pat[NPAT];   // pattern center masks
    __shared__ u64 s_fixed;       // 7x7 influence, center 3x3 cleared
    __shared__ u64 s_targ;        // 5x5 target at rows/cols 1..5
    __shared__ u64 s_best;        // (float_bits << 32) | pattern_idx

    const int b    = blockIdx.x;
    const int tid  = threadIdx.x;
    const int warp = tid >> 5;
    const int lane = tid & 31;

    const int ry = *ryp, rx = *rxp;
    const float* __restrict__ xb = x + b * 625;
    float* __restrict__ ob = out + b * 625;

    // Warp 0: gather 7x7 influence window (center cleared), periodic indexing.
    if (warp == 0) {
        u64 pf = 0;
        #pragma unroll
        for (int it = 0; it < 2; it++) {
            int item = lane + it * 32;
            if (item < 49) {
                int r = item / 7, c = item % 7;
                if (!(r >= 2 && r <= 4 && c >= 2 && c <= 4)) {
                    int rr = (ry + 23 + r) % 25;
                    int cc = (rx + 23 + c) % 25;
                    if (xb[rr * 25 + cc] != 0.0f) pf |= 1ULL << (r * 8 + c);
                }
            }
        }
        u64 f = ((u64)__reduce_or_sync(0xffffffffu, (unsigned)(pf >> 32)) << 32)
              |  (u64)__reduce_or_sync(0xffffffffu, (unsigned)pf);
        if (lane == 0) s_fixed = f;
    }
    // Warp 1: gather 5x5 target window.
    else if (warp == 1) {
        u64 pt = 0;
        if (lane < 25) {
            int r = lane / 5, c = lane % 5;
            int rr = (ry + 24 + r) % 25;
            int cc = (rx + 24 + c) % 25;
            if (target[b * 625 + rr * 25 + cc] != 0.0f)
                pt |= 1ULL << ((r + 1) * 8 + (c + 1));
        }
        u64 tg = ((u64)__reduce_or_sync(0xffffffffu, (unsigned)(pt >> 32)) << 32)
               |  (u64)__reduce_or_sync(0xffffffffu, (unsigned)pt);
        if (lane == 0) s_targ = tg;
    }
    if (tid == 64) s_best = ~0ULL;

    // All threads: build pattern LUT (2 each) and copy x -> out (3 iters).
    // pi bit k (k=r*3+c) = (p >> (8-k)) & 1; row triple is bit-reversed
    // relative to board column order.
    #pragma unroll
    for (int k = 0; k < 2; k++) {
        int p = tid + k * 256;
        u64 m = 0;
        #pragma unroll
        for (int r = 0; r < 3; r++) {
            unsigned t3 = (p >> (6 - 3 * r)) & 7u;
            unsigned rv = __brev(t3) >> 29;       // reverse 3 bits
            m |= (u64)rv << ((2 + r) * 8 + 2);
        }
        s_pat[p] = m;
    }
    for (int i = tid; i < 625; i += 256) ob[i] = xb[i];

    __syncthreads();

    const u64 fixedB = s_fixed;
    const u64 targ   = s_targ;
    const u64 M    = 0x007F7F7F7F7F7F7FULL;  // col-shift guard
    const u64 CROP = 0x00003E3E3E3E3E00ULL;  // rows 1..5, cols 1..5

    u64 bestKey = ~0ULL;
    #pragma unroll
    for (int k = 0; k < 2; k++) {
        const int p = tid + k * 256;
        u64 board = fixedB | s_pat[p];

        // One Conway step, bit-parallel (carry-save adders).
        u64 n1 = (board << 1) & M;
        u64 n2 = (board >> 1) & M;
        u64 n3 = board << 8;
        u64 n4 = board >> 8;
        u64 n5 = n1 << 8, n6 = n1 >> 8;
        u64 n7 = n2 << 8, n8 = n2 >> 8;

        u64 A = n1 ^ n2, Bb = n1 & n2;
        u64 C = n3 ^ n4, D  = n3 & n4;
        u64 E = n5 ^ n6, F  = n5 & n6;
        u64 G = n7 ^ n8, H  = n7 & n8;

        u64 s1a = A ^ C, c1a = A & C;
        u64 s1b = E ^ G, c1b = E & G;
        u64 lo  = s1a ^ s1b, clo = s1a & s1b;

        u64 u = Bb ^ D,  uc = Bb & D;
        u64 v = F  ^ H,  vc = F  & H;
        u64 w = c1a ^ c1b, wc = c1a & c1b;
        u64 pp = u ^ v,  pc = u & v;
        u64 q  = pp ^ w, qc = pp & w;
        u64 r0 = q ^ clo, rc = q & clo;
        u64 K  = uc | vc | wc | pc | qc | rc;

        u64 next = r0 & ~K & (lo | board);

        int err = __popcll((next & CROP) ^ targ);
        float seeded = (float)err + noise[b * NPAT + p] * 0.5f;
        u64 key = ((u64)__float_as_uint(seeded) << 32) | (unsigned)p;
        if (key < bestKey) bestKey = key;
    }

    // Warp argmin (packed key => value min with first-index tiebreak),
    // then one shared atomicMin per warp.
    #pragma unroll
    for (int s = 16; s; s >>= 1) {
        u64 o = __shfl_xor_sync(0xffffffffu, bestKey, s);
        if (o < bestKey) bestKey = o;
    }
    if (lane == 0) atomicMin(&s_best, bestKey);

    __syncthreads();   // publishes s_best; orders copy stores before patch

    if (tid < 9) {
        int best = (int)(unsigned)s_best;
        float vv = ((best >> (8 - tid)) & 1) ? 1.0f : 0.0f;
        ob[(ry + tid / 3) * 25 + (rx + tid % 3)] = vv;
    }
}

extern "C" void kernel_launch(void* const* d_in, const int* in_sizes, int n_in,
                              void* d_out, int out_size)
{
    const float* x      = (const float*)d_in[0];
    const float* target = (const float*)d_in[1];
    const float* noise  = (const float*)d_in[2];
    const int*   ryp    = (const int*)d_in[3];
    const int*   rxp    = (const int*)d_in[4];
    float* out = (float*)d_out;

    int B = in_sizes[0] / 625;
    bcl_kernel<<<B, 256>>>(x, target, noise, ryp, rxp, out);
}

// round 5
// speedup vs baseline: 1.7923x; 1.3231x over previous
#include <cuda_runtime.h>
#include <cstdint>

// BestChangeLayer: B batches, 25x25 binary grids, 512 candidate 3x3 patterns,
// one Conway step on a 7x7 window, L1 error on inner 5x5 vs target,
// argmin(err + 0.5*noise), write winning pattern into x at (ry, rx).
//
// Bitboards: 7x7 packed in u64 at bit (r*8 + c).
// 128 threads/block, one batch per block, 4 patterns per thread.
// Patterns p = tid + 128k share low 7 bits; k only toggles board bits 18/19.

#define NPAT 512
typedef unsigned long long u64;

__global__ __launch_bounds__(128, 8)
void bcl_kernel(const float* __restrict__ x,
                const float* __restrict__ target,
                const float* __restrict__ noise,
                const int* __restrict__ ryp,
                const int* __restrict__ rxp,
                float* __restrict__ out)
{
    __shared__ u64 s_fixed;   // 7x7 influence, center 3x3 cleared
    __shared__ u64 s_targ;    // 5x5 target at rows/cols 1..5
    __shared__ u64 s_best;    // (float_bits << 32) | pattern_idx

    const int b    = blockIdx.x;
    const int tid  = threadIdx.x;
    const int warp = tid >> 5;
    const int lane = tid & 31;

    const float* __restrict__ xb = x + b * 625;
    float* __restrict__ ob = out + b * 625;

    // ---- Prefetch (independent of ry/rx, overlaps the gather chain) ----
    float nz0 = noise[b * NPAT + tid];
    float nz1 = noise[b * NPAT + tid + 128];
    float nz2 = noise[b * NPAT + tid + 256];
    float nz3 = noise[b * NPAT + tid + 384];

    float c0 = xb[tid];
    float c1 = xb[tid + 128];
    float c2 = xb[tid + 256];
    float c3 = xb[tid + 384];
    float c4 = (tid < 113) ? xb[tid + 512] : 0.0f;

    const int ry = *ryp, rx = *rxp;

    if (tid == 64) s_best = ~0ULL;

    // Warp 0: gather 7x7 influence window (center cleared), periodic idx.
    if (warp == 0) {
        u64 pf = 0;
        #pragma unroll
        for (int it = 0; it < 2; it++) {
            int item = lane + it * 32;
            if (item < 49) {
                int r = item / 7, c = item % 7;
                if (!(r >= 2 && r <= 4 && c >= 2 && c <= 4)) {
                    int rr = (ry + 23 + r) % 25;
                    int cc = (rx + 23 + c) % 25;
                    if (xb[rr * 25 + cc] != 0.0f) pf |= 1ULL << (r * 8 + c);
                }
            }
        }
        u64 f = ((u64)__reduce_or_sync(0xffffffffu, (unsigned)(pf >> 32)) << 32)
              |  (u64)__reduce_or_sync(0xffffffffu, (unsigned)pf);
        if (lane == 0) s_fixed = f;
    }
    // Warp 1: gather 5x5 target window.
    else if (warp == 1) {
        u64 pt = 0;
        if (lane < 25) {
            int r = lane / 5, c = lane % 5;
            int rr = (ry + 24 + r) % 25;
            int cc = (rx + 24 + c) % 25;
            if (target[b * 625 + rr * 25 + cc] != 0.0f)
                pt |= 1ULL << ((r + 1) * 8 + (c + 1));
        }
        u64 tg = ((u64)__reduce_or_sync(0xffffffffu, (unsigned)(pt >> 32)) << 32)
               |  (u64)__reduce_or_sync(0xffffffffu, (unsigned)pt);
        if (lane == 0) s_targ = tg;
    }

    // Copy x -> out (stores; loads already issued above).
    ob[tid]       = c0;
    ob[tid + 128] = c1;
    ob[tid + 256] = c2;
    ob[tid + 384] = c3;
    if (tid < 113) ob[tid + 512] = c4;

    // Base pattern mask from low 7 bits of tid:
    //   bit6 -> board bit 20 (r0c2); bits5..3 -> 26..28 (row1);
    //   bits2..0 -> 34..36 (row2).  pi bit k = (p >> (8-k)) & 1.
    u64 base = ((u64)((tid >> 6) & 1) << 20)
             | ((u64)(__brev((tid >> 3) & 7) >> 29) << 26)
             | ((u64)(__brev(tid & 7) >> 29) << 34);

    __syncthreads();

    const u64 fixedB = s_fixed;
    const u64 targ   = s_targ;
    const u64 M    = 0x007F7F7F7F7F7F7FULL;  // col-shift guard
    const u64 CROP = 0x00003E3E3E3E3E00ULL;  // rows 1..5, cols 1..5

    u64 bestKey = ~0ULL;

    // Fully unrolled eval for pattern p = tid + 128*K, extra center bits EX.
#define EVAL_ONE(K, EX, NZ)                                                  \
    {                                                                        \
        u64 board = fixedB | base | (EX);                                    \
        u64 n1 = (board << 1) & M;                                           \
        u64 n2 = (board >> 1) & M;                                           \
        u64 n3 = board << 8;                                                 \
        u64 n4 = board >> 8;                                                 \
        u64 n5 = n1 << 8, n6 = n1 >> 8;                                      \
        u64 n7 = n2 << 8, n8 = n2 >> 8;                                      \
        u64 A = n1 ^ n2, Bb = n1 & n2;                                       \
        u64 C = n3 ^ n4, D  = n3 & n4;                                       \
        u64 E = n5 ^ n6, F  = n5 & n6;                                       \
        u64 G = n7 ^ n8, H  = n7 & n8;                                       \
        u64 s1a = A ^ C, c1a = A & C;                                        \
        u64 s1b = E ^ G, c1b = E & G;                                        \
        u64 lo  = s1a ^ s1b, clo = s1a & s1b;                                \
        u64 u = Bb ^ D,  uc = Bb & D;                                        \
        u64 v = F  ^ H,  vc = F  & H;                                        \
        u64 w = c1a ^ c1b, wc = c1a & c1b;                                   \
        u64 pp = u ^ v,  pc = u & v;                                         \
        u64 q  = pp ^ w, qc = pp & w;                                        \
        u64 r0 = q ^ clo, rc = q & clo;                                      \
        u64 Kk = uc | vc | wc | pc | qc | rc;                                \
        u64 next = r0 & ~Kk & (lo | board);                                  \
        int err = __popcll((next & CROP) ^ targ);                            \
        float seeded = (float)err + (NZ) * 0.5f;                             \
        u64 key = ((u64)__float_as_uint(seeded) << 32)                       \
                | (unsigned)(tid + 128 * (K));                               \
        if (key < bestKey) bestKey = key;                                    \
    }

    // k toggles pattern bits r0c0 (board bit 18) and r0c1 (board bit 19).
    EVAL_ONE(0, 0ULL, nz0)
    EVAL_ONE(1, 1ULL << 19, nz1)
    EVAL_ONE(2, 1ULL << 18, nz2)
    EVAL_ONE(3, (1ULL << 18) | (1ULL << 19), nz3)
#undef EVAL_ONE

    // Warp argmin (packed key => value min, first-index tiebreak).
    #pragma unroll
    for (int s = 16; s; s >>= 1) {
        u64 o = __shfl_xor_sync(0xffffffffu, bestKey, s);
        if (o < bestKey) bestKey = o;
    }
    if (lane == 0) atomicMin(&s_best, bestKey);

    __syncthreads();   // publishes s_best; orders copy stores before patch

    if (tid < 9) {
        int best = (int)(unsigned)s_best;
        float vv = ((best >> (8 - tid)) & 1) ? 1.0f : 0.0f;
        ob[(ry + tid / 3) * 25 + (rx + tid % 3)] = vv;
    }
}

extern "C" void kernel_launch(void* const* d_in, const int* in_sizes, int n_in,
                              void* d_out, int out_size)
{
    const float* x      = (const float*)d_in[0];
    const float* target = (const float*)d_in[1];
    const float* noise  = (const float*)d_in[2];
    const int*   ryp    = (const int*)d_in[3];
    const int*   rxp    = (const int*)d_in[4];
    float* out = (float*)d_out;

    int B = in_sizes[0] / 625;
    bcl_kernel<<<B, 128>>>(x, target, noise, ryp, rxp, out);
}

// round 6
// speedup vs baseline: 1.8203x; 1.0156x over previous
#include <cuda_runtime.h>
#include <cstdint>

// BestChangeLayer: B batches, 25x25 binary grids, 512 candidate 3x3 patterns,
// one Conway step on a 7x7 window, L1 error on inner 5x5 vs target,
// argmin(err + 0.5*noise), write winning pattern into x at (ry, rx).
//
// Bitboards: 7x7 packed in u64 at bit (r*8 + c).
// 128 threads/block, one batch per block, 4 patterns per thread.
// Each warp gathers its own windows (no inter-warp dependency until the
// single final barrier). Patterns p = tid + 128k share low 7 bits; k only
// toggles board bits 18/19.

#define NPAT 512
typedef unsigned long long u64;

__global__ __launch_bounds__(128, 8)
void bcl_kernel(const float* __restrict__ x,
                const float* __restrict__ target,
                const float* __restrict__ noise,
                const int* __restrict__ ryp,
                const int* __restrict__ rxp,
                float* __restrict__ out)
{
    __shared__ u64 sk[4];     // per-warp best (float_bits << 32) | pattern_idx

    const int b    = blockIdx.x;
    const int tid  = threadIdx.x;
    const int warp = tid >> 5;
    const int lane = tid & 31;

    const float* __restrict__ xb = x + b * 625;
    const float* __restrict__ tb = target + b * 625;
    float* __restrict__ ob = out + b * 625;

    // ---- Prefetch (independent of ry/rx, overlaps the gather chain) ----
    float nz0 = noise[b * NPAT + tid];
    float nz1 = noise[b * NPAT + tid + 128];
    float nz2 = noise[b * NPAT + tid + 256];
    float nz3 = noise[b * NPAT + tid + 384];

    float c0 = xb[tid];
    float c1 = xb[tid + 128];
    float c2 = xb[tid + 256];
    float c3 = xb[tid + 384];
    float c4 = (tid < 113) ? xb[tid + 512] : 0.0f;

    const int ry = *ryp, rx = *rxp;

    // Every warp gathers BOTH windows itself (periodic indexing).
    // items 0..48: 7x7 influence window (center 3x3 cleared)
    // items 49..73: 5x5 target window
    u64 pf = 0, pt = 0;
    #pragma unroll
    for (int it = 0; it < 3; it++) {
        int item = lane + it * 32;
        if (item < 49) {
            int r = item / 7, c = item % 7;
            if (!(r >= 2 && r <= 4 && c >= 2 && c <= 4)) {
                int rr = (ry + 23 + r) % 25;
                int cc = (rx + 23 + c) % 25;
                if (xb[rr * 25 + cc] != 0.0f) pf |= 1ULL << (r * 8 + c);
            }
        } else if (item < 74) {
            int k = item - 49;
            int r = k / 5, c = k % 5;
            int rr = (ry + 24 + r) % 25;
            int cc = (rx + 24 + c) % 25;
            if (tb[rr * 25 + cc] != 0.0f) pt |= 1ULL << ((r + 1) * 8 + (c + 1));
        }
    }
    const u64 fixedB =
          ((u64)__reduce_or_sync(0xffffffffu, (unsigned)(pf >> 32)) << 32)
        |  (u64)__reduce_or_sync(0xffffffffu, (unsigned)pf);
    const u64 targ =
          ((u64)__reduce_or_sync(0xffffffffu, (unsigned)(pt >> 32)) << 32)
        |  (u64)__reduce_or_sync(0xffffffffu, (unsigned)pt);

    // Copy x -> out (stores; loads already issued above).
    ob[tid]       = c0;
    ob[tid + 128] = c1;
    ob[tid + 256] = c2;
    ob[tid + 384] = c3;
    if (tid < 113) ob[tid + 512] = c4;

    // Base pattern mask from low 7 bits of tid:
    //   bit6 -> board bit 20 (r0c2); bits5..3 -> 26..28 (row1);
    //   bits2..0 -> 34..36 (row2).  pi bit k = (p >> (8-k)) & 1.
    const u64 base = ((u64)((tid >> 6) & 1) << 20)
                   | ((u64)(__brev((tid >> 3) & 7) >> 29) << 26)
                   | ((u64)(__brev(tid & 7) >> 29) << 34);

    const u64 M    = 0x007F7F7F7F7F7F7FULL;  // col-shift guard
    const u64 CROP = 0x00003E3E3E3E3E00ULL;  // rows 1..5, cols 1..5

    u64 bestKey = ~0ULL;

    // Fully unrolled eval for pattern p = tid + 128*K, extra center bits EX.
#define EVAL_ONE(K, EX, NZ)                                                  \
    {                                                                        \
        u64 board = fixedB | base | (EX);                                    \
        u64 n1 = (board << 1) & M;                                           \
        u64 n2 = (board >> 1) & M;                                           \
        u64 n3 = board << 8;                                                 \
        u64 n4 = board >> 8;                                                 \
        u64 n5 = n1 << 8, n6 = n1 >> 8;                                      \
        u64 n7 = n2 << 8, n8 = n2 >> 8;                                      \
        u64 A = n1 ^ n2, Bb = n1 & n2;                                       \
        u64 C = n3 ^ n4, D  = n3 & n4;                                       \
        u64 E = n5 ^ n6, F  = n5 & n6;                                       \
        u64 G = n7 ^ n8, H  = n7 & n8;                                       \
        u64 s1a = A ^ C, c1a = A & C;                                        \
        u64 s1b = E ^ G, c1b = E & G;                                        \
        u64 lo  = s1a ^ s1b, clo = s1a & s1b;                                \
        u64 u = Bb ^ D,  uc = Bb & D;                                        \
        u64 v = F  ^ H,  vc = F  & H;                                        \
        u64 w = c1a ^ c1b, wc = c1a & c1b;                                   \
        u64 pp = u ^ v,  pc = u & v;                                         \
        u64 q  = pp ^ w, qc = pp & w;                                        \
        u64 r0 = q ^ clo;                                                    \
        u64 Kk = uc | vc | wc | pc | qc | (q & clo);                         \
        u64 next = r0 & ~Kk & (lo | board);                                  \
        int err = __popcll((next & CROP) ^ targ);                            \
        float seeded = (float)err + (NZ) * 0.5f;                             \
        u64 key = ((u64)__float_as_uint(seeded) << 32)                       \
                | (unsigned)(tid + 128 * (K));                               \
        if (key < bestKey) bestKey = key;                                    \
    }

    // k toggles pattern bits r0c0 (board bit 18) and r0c1 (board bit 19).
    EVAL_ONE(0, 0ULL, nz0)
    EVAL_ONE(1, 1ULL << 19, nz1)
    EVAL_ONE(2, 1ULL << 18, nz2)
    EVAL_ONE(3, (1ULL << 18) | (1ULL << 19), nz3)
#undef EVAL_ONE

    // Warp argmin (packed key => value min, first-index tiebreak).
    #pragma unroll
    for (int s = 16; s; s >>= 1) {
        u64 o = __shfl_xor_sync(0xffffffffu, bestKey, s);
        if (o < bestKey) bestKey = o;
    }
    if (lane == 0) sk[warp] = bestKey;

    __syncthreads();   // publishes sk; orders copy stores before patch

    if (tid < 9) {
        u64 k0 = sk[0];
        if (sk[1] < k0) k0 = sk[1];
        if (sk[2] < k0) k0 = sk[2];
        if (sk[3] < k0) k0 = sk[3];
        int best = (int)(unsigned)k0;
        float vv = ((best >> (8 - tid)) & 1) ? 1.0f : 0.0f;
        ob[(ry + tid / 3) * 25 + (rx + tid % 3)] = vv;
    }
}

extern "C" void kernel_launch(void* const* d_in, const int* in_sizes, int n_in,
                              void* d_out, int out_size)
{
    const float* x      = (const float*)d_in[0];
    const float* target = (const float*)d_in[1];
    const float* noise  = (const float*)d_in[2];
    const int*   ryp    = (const int*)d_in[3];
    const int*   rxp    = (const int*)d_in[4];
    float* out = (float*)d_out;

    int B = in_sizes[0] / 625;
    bcl_kernel<<<B, 128>>>(x, target, noise, ryp, rxp, out);
}

// round 7
// speedup vs baseline: 2.0897x; 1.1480x over previous
#include <cuda_runtime.h>
#include <cstdint>

// BestChangeLayer: B batches, 25x25 binary grids, 512 candidate 3x3 patterns,
// one Conway step on a 7x7 window, L1 error on inner 5x5 vs target,
// argmin(err + 0.5*noise), write winning pattern into x at (ry, rx).
//
// Bitboards: 7x7 packed in u64 at bit (r*8 + c).
// 128 threads/block, one batch per block, 4 patterns per thread.
// Warp specialization: w0 gathers fixed window, w1 gathers target, w2-3 copy.
// Shared CSA: neighbor counts of the common board computed once per thread;
// the 4 variants (center bits 18/19) ripple-add constant neighbor masks.

#define NPAT 512
typedef unsigned long long u64;

__global__ __launch_bounds__(128, 10)
void bcl_kernel(const float* __restrict__ x,
                const float* __restrict__ target,
                const float* __restrict__ noise,
                const int* __restrict__ ryp,
                const int* __restrict__ rxp,
                float* __restrict__ out)
{
    __shared__ u64 s_fixed;   // 7x7 influence, center 3x3 cleared
    __shared__ u64 s_targ;    // 5x5 target at rows/cols 1..5
    __shared__ u64 sk[4];     // per-warp best (float_bits << 32) | pattern_idx

    const int b    = blockIdx.x;
    const int tid  = threadIdx.x;
    const int warp = tid >> 5;
    const int lane = tid & 31;

    const float* __restrict__ xb = x + b * 625;
    float* __restrict__ ob = out + b * 625;

    // Noise prefetch (needed only at the very end -> latency fully hidden).
    float nz0 = noise[b * NPAT + tid];
    float nz1 = noise[b * NPAT + tid + 128];
    float nz2 = noise[b * NPAT + tid + 256];
    float nz3 = noise[b * NPAT + tid + 384];

    const int ry = *ryp, rx = *rxp;

    if (warp == 0) {
        // Gather 7x7 influence window (center 3x3 cleared), periodic idx.
        u64 pf = 0;
        #pragma unroll
        for (int it = 0; it < 2; it++) {
            int item = lane + it * 32;
            if (item < 49) {
                int r = item / 7, c = item % 7;
                if (!(r >= 2 && r <= 4 && c >= 2 && c <= 4)) {
                    int rr = (ry + 23 + r) % 25;
                    int cc = (rx + 23 + c) % 25;
                    if (xb[rr * 25 + cc] != 0.0f) pf |= 1ULL << (r * 8 + c);
                }
            }
        }
        u64 f = ((u64)__reduce_or_sync(0xffffffffu, (unsigned)(pf >> 32)) << 32)
              |  (u64)__reduce_or_sync(0xffffffffu, (unsigned)pf);
        if (lane == 0) s_fixed = f;
    } else if (warp == 1) {
        // Gather 5x5 target window.
        u64 pt = 0;
        if (lane < 25) {
            int r = lane / 5, c = lane % 5;
            int rr = (ry + 24 + r) % 25;
            int cc = (rx + 24 + c) % 25;
            if (target[b * 625 + rr * 25 + cc] != 0.0f)
                pt |= 1ULL << ((r + 1) * 8 + (c + 1));
        }
        u64 tg = ((u64)__reduce_or_sync(0xffffffffu, (unsigned)(pt >> 32)) << 32)
               |  (u64)__reduce_or_sync(0xffffffffu, (unsigned)pt);
        if (lane == 0) s_targ = tg;
    } else {
        // Warps 2-3: copy x -> out (64 threads x 10 elements, 2 rounds of 5).
        int t2 = tid - 64;
        #pragma unroll
        for (int rd = 0; rd < 2; rd++) {
            int bi = t2 + rd * 320;
            float v0, v1, v2, v3, v4;
            if (bi       < 625) v0 = xb[bi];
            if (bi + 64  < 625) v1 = xb[bi + 64];
            if (bi + 128 < 625) v2 = xb[bi + 128];
            if (bi + 192 < 625) v3 = xb[bi + 192];
            if (bi + 256 < 625) v4 = xb[bi + 256];
            if (bi       < 625) ob[bi]       = v0;
            if (bi + 64  < 625) ob[bi + 64]  = v1;
            if (bi + 128 < 625) ob[bi + 128] = v2;
            if (bi + 192 < 625) ob[bi + 192] = v3;
            if (bi + 256 < 625) ob[bi + 256] = v4;
        }
    }

    // Base pattern mask from low 7 bits of tid:
    //   bit6 -> board bit 20 (r0c2); bits5..3 -> 26..28 (row1);
    //   bits2..0 -> 34..36 (row2).  pi bit k = (p >> (8-k)) & 1.
    const u64 base = ((u64)((tid >> 6) & 1) << 20)
                   | ((u64)(__brev((tid >> 3) & 7) >> 29) << 26)
                   | ((u64)(__brev(tid & 7) >> 29) << 34);

    __syncthreads();

    const u64 targ = s_targ;
    const u64 Bc   = s_fixed | base;            // common board (no bits 18/19)
    const u64 M    = 0x007F7F7F7F7F7F7FULL;     // col-shift guard
    const u64 CROP = 0x00003E3E3E3E3E00ULL;     // rows 1..5, cols 1..5
    const u64 B18  = 1ULL << 18, B19 = 1ULL << 19;
    // Constant neighbor masks of center cells (2,2) and (2,3):
    const u64 M18 = 0x000000000E0A0E00ULL;      // bits 9,10,11,17,19,25,26,27
    const u64 M19 = 0x000000001C141C00ULL;      // bits 10,11,12,18,20,26,27,28

    // One CSA over the 8 neighbor planes of Bc -> bit-sliced count:
    //   c0 = count bit0, c1 = parity of weight-2 sum S, hi = (S >= 2).
    // alive test: count==3 or (cell & count==2)  <=>  c1 & ~hi & (c0 | cell).
    u64 n1 = (Bc << 1) & M;
    u64 n2 = (Bc >> 1) & M;
    u64 n3 = Bc << 8,  n4 = Bc >> 8;
    u64 n5 = n1 << 8,  n6 = n1 >> 8;
    u64 n7 = n2 << 8,  n8 = n2 >> 8;

    u64 a1 = n1 ^ n2, b1 = n1 & n2;
    u64 a2 = n3 ^ n4, b2 = n3 & n4;
    u64 a3 = n5 ^ n6, b3 = n5 & n6;
    u64 a4 = n7 ^ n8, b4 = n7 & n8;

    u64 s1 = a1 ^ a2, t1 = a1 & a2;
    u64 s2 = a3 ^ a4, t2 = a3 & a4;
    u64 c0 = s1 ^ s2, u0 = s1 & s2;

    u64 p1 = b1 ^ b2, q1 = b1 & b2;
    u64 p2 = b3 ^ b4, q2 = b3 & b4;
    u64 p3 = t1 ^ t2, q3 = t1 & t2;
    u64 r1 = p1 ^ p2, w1 = p1 & p2;
    u64 r2 = p3 ^ u0, w2 = p3 & u0;
    u64 c1 = r1 ^ r2, w3 = r1 & r2;
    u64 hi = q1 | q2 | q3 | w1 | w2 | w3;

    u64 bestKey = ~0ULL;

#define FIN(NEXT, P, NZ)                                                     \
    {                                                                        \
        int err = __popcll(((NEXT) & CROP) ^ targ);                          \
        float sd = (float)err + (NZ) * 0.5f;                                 \
        u64 key = ((u64)__float_as_uint(sd) << 32) | (unsigned)(P);          \
        if (key < bestKey) bestKey = key;                                    \
    }

    // Variant 0: no center toggles.
    {
        u64 nx = c1 & ~hi & (c0 | Bc);
        FIN(nx, tid, nz0)
    }
    // Variant 1: +bit19 (pattern bit r0c1). Add M19 to the count.
    {
        u64 k0 = c0 & M19, a0 = c0 ^ M19;
        u64 av = c1 ^ k0,  h  = hi | (c1 & k0);
        u64 nx = av & ~h & (a0 | Bc | B19);
        FIN(nx, tid + 128, nz1)
    }
    // Variant 2: +bit18. Add M18.
    {
        u64 k0 = c0 & M18, a0 = c0 ^ M18;
        u64 av = c1 ^ k0,  h  = hi | (c1 & k0);
        u64 nx = av & ~h & (a0 | Bc | B18);
        FIN(nx, tid + 256, nz2)
    }
    // Variant 3: +bit18 and +bit19. Sequential ripple adds (exact).
    {
        u64 k0 = c0 & M18, a0 = c0 ^ M18;
        u64 av = c1 ^ k0,  h1 = hi | (c1 & k0);
        u64 k1 = a0 & M19, g0 = a0 ^ M19;
        u64 gv = av ^ k1,  h2 = h1 | (av & k1);
        u64 nx = gv & ~h2 & (g0 | Bc | B18 | B19);
        FIN(nx, tid + 384, nz3)
    }
#undef FIN

    // Warp argmin (packed key => value min, first-index tiebreak).
    #pragma unroll
    for (int s = 16; s; s >>= 1) {
        u64 o = __shfl_xor_sync(0xffffffffu, bestKey, s);
        if (o < bestKey) bestKey = o;
    }
    if (lane == 0) sk[warp] = bestKey;

    __syncthreads();   // publishes sk; orders copy stores before patch

    if (tid < 9) {
        u64 k0 = sk[0];
        if (sk[1] < k0) k0 = sk[1];
        if (sk[2] < k0) k0 = sk[2];
        if (sk[3] < k0) k0 = sk[3];
        int best = (int)(unsigned)k0;
        float vv = ((best >> (8 - tid)) & 1) ? 1.0f : 0.0f;
        ob[(ry + tid / 3) * 25 + (rx + tid % 3)] = vv;
    }
}

extern "C" void kernel_launch(void* const* d_in, const int* in_sizes, int n_in,
                              void* d_out, int out_size)
{
    const float* x      = (const float*)d_in[0];
    const float* target = (const float*)d_in[1];
    const float* noise  = (const float*)d_in[2];
    const int*   ryp    = (const int*)d_in[3];
    const int*   rxp    = (const int*)d_in[4];
    float* out = (float*)d_out;

    int B = in_sizes[0] / 625;
    bcl_kernel<<<B, 128>>>(x, target, noise, ryp, rxp, out);
}